// round 15
// baseline (speedup 1.0000x reference)
#include <cuda_runtime.h>
#include <cuda_fp16.h>
#include <math.h>
#include <stdint.h>

// Problem constants
#define NN 49152
#define EE 196608
#define BB 1024
#define SS 48
#define DD 256
#define GD 512
#define KDIM 1024
#define CAP 32

// ---------------- scratch ----------------
__device__ unsigned g_odd_or;
__device__ __align__(16) int g_degi[NN];
__device__ __align__(16) int g_cnti[NN];
__device__ __align__(16) int g_brow[NN * CAP];
__device__ __align__(16) int g_bdst[NN * CAP];
__device__ __align__(16) float g_dinv[NN];
__device__ __align__(16) float g_cntinv[NN];
__device__ __align__(16) float g_feat1[(size_t)NN * 1024];
__device__ __align__(16) float g_h1[(size_t)NN * 512];
__device__ __align__(16) float g_agg2[(size_t)NN * 512];
__device__ __align__(16) float g_pool[(size_t)BB * 1024];
__device__ __align__(16) float g_w1[(size_t)GD * KDIM];
__device__ __align__(16) float g_w2[(size_t)GD * KDIM];

// ---------------- helpers ----------------
__device__ __forceinline__ float gelu_exact(float x) {
    return 0.5f * x * (1.0f + erff(x * 0.7071067811865476f));
}
__device__ __forceinline__ void fma4(float4& a, float w, float4 v) {
    a.x = fmaf(w, v.x, a.x); a.y = fmaf(w, v.y, a.y);
    a.z = fmaf(w, v.z, a.z); a.w = fmaf(w, v.w, a.w);
}
__device__ __forceinline__ void add4(float4& a, float4 v) {
    a.x += v.x; a.y += v.y; a.z += v.z; a.w += v.w;
}
__device__ __forceinline__ float4 mul4(float4 a, float s) {
    return make_float4(a.x * s, a.y * s, a.z * s, a.w * s);
}
__device__ __forceinline__ unsigned h2pack(float a, float b) {
    __half2 h = __floats2half2_rn(a, b);
    return *(unsigned*)&h;
}

// ---------------- edge prep ----------------
__global__ void k_zero_scan(const unsigned* __restrict__ buf) {
    int t = blockIdx.x * blockDim.x + threadIdx.x;
    if (t == 0) g_odd_or = 0u;
    if (t < NN) { g_degi[t] = 0; g_cnti[t] = 0; }
    unsigned v = 0u;
    for (int i = t; i < EE; i += gridDim.x * blockDim.x)
        v |= buf[2 * i + 1];
    v = __reduce_or_sync(0xffffffffu, v);
    if ((threadIdx.x & 31) == 0 && v) atomicOr((unsigned*)&g_odd_or, v);
}

__global__ void k_convert(const unsigned* __restrict__ buf) {
    int e = blockIdx.x * blockDim.x + threadIdx.x;
    if (e >= EE) return;
    bool is64 = (g_odd_or == 0u);
    int r, c;
    if (is64) { r = (int)buf[2 * e]; c = (int)buf[2 * (EE + e)]; }
    else      { r = (int)buf[e];     c = (int)buf[EE + e]; }
    r = min(max(r, 0), NN - 1);
    c = min(max(c, 0), NN - 1);
    int p = atomicAdd(&g_degi[r], 1);
    if (p < CAP) g_brow[r * CAP + p] = c;
    int q = atomicAdd(&g_cnti[c], 1);
    if (q < CAP) g_bdst[c * CAP + q] = r;
}

__global__ void k_prep(const float4* __restrict__ wl1, const float4* __restrict__ wr1,
                       const float4* __restrict__ wl2, const float4* __restrict__ wr2) {
    int idx = blockIdx.x * blockDim.x + threadIdx.x;
    if (idx < NN) {
        int d = g_degi[idx];
        g_dinv[idx] = d > 0 ? rsqrtf((float)d) : 0.f;
        int c = g_cnti[idx];
        g_cntinv[idx] = 1.0f / (float)max(c, 1);
    }
    if (idx < GD * 256) {
        int j = idx >> 8, q = idx & 255;
        float4 v1 = (q < 128) ? __ldg(&wl1[(size_t)j * 128 + q]) : __ldg(&wr1[(size_t)j * 128 + q - 128]);
        float4 v2 = (q < 128) ? __ldg(&wl2[(size_t)j * 128 + q]) : __ldg(&wr2[(size_t)j * 128 + q - 128]);
        ((float4*)g_w1)[idx] = v1;
        ((float4*)g_w2)[idx] = v2;
    }
}

// ---------------- gathers ----------------
__global__ void k_lap_gather(const float4* __restrict__ x4) {
    int n = (blockIdx.x * blockDim.x + threadIdx.x) >> 5;
    int lane = threadIdx.x & 31;
    if (n >= NN) return;
    float dr = g_dinv[n];
    int deg = min(g_degi[n], CAP);
    float4 a0 = __ldg(&x4[(size_t)n * 64 + lane]);
    float4 a1 = __ldg(&x4[(size_t)n * 64 + 32 + lane]);
    float4 s0 = a0, s1 = a1;
    for (int j = 0; j < deg; j++) {
        int c = g_brow[n * CAP + j];
        float wt = -dr * g_dinv[c];
        fma4(s0, wt, __ldg(&x4[(size_t)c * 64 + lane]));
        fma4(s1, wt, __ldg(&x4[(size_t)c * 64 + 32 + lane]));
    }
    float4* dst = (float4*)(g_feat1 + (size_t)n * 1024);
    dst[128 + lane] = a0;
    dst[160 + lane] = a1;
    dst[192 + lane] = s0;
    dst[224 + lane] = s1;
}

__global__ void k_agg1_gather() {
    int n = (blockIdx.x * blockDim.x + threadIdx.x) >> 5;
    int lane = threadIdx.x & 31;
    if (n >= NN) return;
    int cnt = min(g_cnti[n], CAP);
    float4 acc0 = make_float4(0, 0, 0, 0), acc1 = acc0, acc2 = acc0, acc3 = acc0;
    for (int j = 0; j < cnt; j++) {
        int s = g_bdst[n * CAP + j];
        const float4* src = (const float4*)(g_feat1 + (size_t)s * 1024 + 512);
        add4(acc0, __ldg(src + lane));
        add4(acc1, __ldg(src + 32 + lane));
        add4(acc2, __ldg(src + 64 + lane));
        add4(acc3, __ldg(src + 96 + lane));
    }
    float ci = g_cntinv[n];
    float4* dst = (float4*)(g_feat1 + (size_t)n * 1024);
    dst[lane]      = mul4(acc0, ci);
    dst[32 + lane] = mul4(acc1, ci);
    dst[64 + lane] = mul4(acc2, ci);
    dst[96 + lane] = mul4(acc3, ci);
}

__global__ void k_agg2_gather() {
    int n = (blockIdx.x * blockDim.x + threadIdx.x) >> 5;
    int lane = threadIdx.x & 31;
    if (n >= NN) return;
    int cnt = min(g_cnti[n], CAP);
    float4 acc0 = make_float4(0, 0, 0, 0), acc1 = acc0, acc2 = acc0, acc3 = acc0;
    for (int j = 0; j < cnt; j++) {
        int s = g_bdst[n * CAP + j];
        const float4* src = (const float4*)(g_h1 + (size_t)s * 512);
        add4(acc0, __ldg(src + lane));
        add4(acc1, __ldg(src + 32 + lane));
        add4(acc2, __ldg(src + 64 + lane));
        add4(acc3, __ldg(src + 96 + lane));
    }
    float ci = g_cntinv[n];
    float4* dst = (float4*)(g_agg2 + (size_t)n * 512);
    dst[lane]      = mul4(acc0, ci);
    dst[32 + lane] = mul4(acc1, ci);
    dst[64 + lane] = mul4(acc2, ci);
    dst[96 + lane] = mul4(acc3, ci);
}

__global__ void k_pool() {
    int b = blockIdx.x;
    int f = blockIdx.y * 128 + threadIdx.x;
    float s1 = 0.f, s2 = 0.f;
    int n0 = b * SS;
    #pragma unroll 4
    for (int s = 0; s < SS; s++) {
        int n = n0 + s;
        s1 += g_agg2[(size_t)n * 512 + f];
        s2 += g_h1[(size_t)n * 512 + f];
    }
    const float inv = 1.0f / 48.0f;
    g_pool[(size_t)b * 1024 + f] = s1 * inv;
    g_pool[(size_t)b * 1024 + 512 + f] = s2 * inv;
}

// ---------------- fp16 NT GEMM (m16n8k16), double-buffered smem ----------------
// C[M,512] = act(A[M,1024] @ W[512,1024]^T + bias)
// smem holds half2 words; fragment addressing identical to the proven tf32
// stride-20 conflict-free layout (reads stay 32-bit). fp16 mantissa (10 bits)
// == tf32 mantissa, fp32 HW accum -> same error class, 2x MMA throughput.
template <bool GELU>
__device__ __forceinline__ void gemm_body(const float* __restrict__ A,
                                          const float* __restrict__ W,
                                          const float* __restrict__ bias,
                                          float* __restrict__ C) {
    __shared__ unsigned Ah[2][128 * 20];  // half2 words, row stride 20
    __shared__ unsigned Bh[2][128 * 20];
    const int K = KDIM;
    int ntile = blockIdx.x, mtile = blockIdx.y;
    int row0 = mtile * 128, col0 = ntile * 128;
    int tid = threadIdx.x, lane = tid & 31, warp = tid >> 5;
    int wm = warp & 3, wn = warp >> 2;        // 4 m-warps x 2 n-warps
    int m_off = wm * 32, n_off = wn * 64;     // warp computes 32x64
    int g = lane >> 2, kin = lane & 3;
    int lrow = tid >> 1;                      // 0..127 (one smem row per 2 threads)
    int lcb = tid & 1;                        // col block: halfpairs 0-7 / 8-15

    const float* aptr = A + (size_t)(row0 + lrow) * K + lcb * 16;
    const float* bptr = W + (size_t)(col0 + lrow) * K + lcb * 16;

    float acc[2][8][4];
    #pragma unroll
    for (int mt = 0; mt < 2; mt++)
        #pragma unroll
        for (int nt = 0; nt < 8; nt++)
            #pragma unroll
            for (int i = 0; i < 4; i++) acc[mt][nt][i] = 0.f;

    // store 16 floats (4 float4) as 8 half2 -> 2 STS.128
    auto stage = [&](unsigned* dstbase, const float4* ra) {
        uint4 lo, hi;
        lo.x = h2pack(ra[0].x, ra[0].y); lo.y = h2pack(ra[0].z, ra[0].w);
        lo.z = h2pack(ra[1].x, ra[1].y); lo.w = h2pack(ra[1].z, ra[1].w);
        hi.x = h2pack(ra[2].x, ra[2].y); hi.y = h2pack(ra[2].z, ra[2].w);
        hi.z = h2pack(ra[3].x, ra[3].y); hi.w = h2pack(ra[3].z, ra[3].w);
        uint4* s = (uint4*)(dstbase + lrow * 20 + lcb * 8);
        s[0] = lo; s[1] = hi;
    };

    // prologue: K-tile 0 -> buffer 0
    {
        float4 ra[4], rb[4];
        #pragma unroll
        for (int i = 0; i < 4; i++) {
            ra[i] = *(const float4*)(aptr + i * 4);
            rb[i] = *(const float4*)(bptr + i * 4);
        }
        stage(Ah[0], ra);
        stage(Bh[0], rb);
    }
    __syncthreads();

    int cur = 0;
    for (int kt = 0; kt < K; kt += 32) {
        bool has_next = (kt + 32 < K);
        float4 ra[4], rb[4];
        if (has_next) {
            #pragma unroll
            for (int i = 0; i < 4; i++) {
                ra[i] = *(const float4*)(aptr + kt + 32 + i * 4);
                rb[i] = *(const float4*)(bptr + kt + 32 + i * 4);
            }
        }

        #pragma unroll
        for (int kk = 0; kk < 2; kk++) {   // two K=16 steps per 32-float tile
            unsigned af[2][4];
            #pragma unroll
            for (int mt = 0; mt < 2; mt++) {
                int mr = m_off + mt * 16 + g;
                af[mt][0] = Ah[cur][mr * 20 + kk * 8 + kin];
                af[mt][1] = Ah[cur][(mr + 8) * 20 + kk * 8 + kin];
                af[mt][2] = Ah[cur][mr * 20 + kk * 8 + kin + 4];
                af[mt][3] = Ah[cur][(mr + 8) * 20 + kk * 8 + kin + 4];
            }
            #pragma unroll
            for (int nt = 0; nt < 8; nt++) {
                int nr = n_off + nt * 8 + g;
                unsigned bf0 = Bh[cur][nr * 20 + kk * 8 + kin];
                unsigned bf1 = Bh[cur][nr * 20 + kk * 8 + kin + 4];
                #pragma unroll
                for (int mt = 0; mt < 2; mt++) {
                    asm volatile(
                        "mma.sync.aligned.m16n8k16.row.col.f32.f16.f16.f32 "
                        "{%0,%1,%2,%3}, {%4,%5,%6,%7}, {%8,%9}, {%0,%1,%2,%3};"
                        : "+f"(acc[mt][nt][0]), "+f"(acc[mt][nt][1]),
                          "+f"(acc[mt][nt][2]), "+f"(acc[mt][nt][3])
                        : "r"(af[mt][0]), "r"(af[mt][1]), "r"(af[mt][2]), "r"(af[mt][3]),
                          "r"(bf0), "r"(bf1));
                }
            }
        }

        if (has_next) {
            int nxt = cur ^ 1;
            stage(Ah[nxt], ra);
            stage(Bh[nxt], rb);
            __syncthreads();
            cur = nxt;
        }
    }

    // epilogue: bias (+gelu), write [M,512] — accumulator layout same as m16n8k8
    #pragma unroll
    for (int mt = 0; mt < 2; mt++) {
        int row = row0 + m_off + mt * 16 + g;
        #pragma unroll
        for (int nt = 0; nt < 8; nt++) {
            int col = col0 + n_off + nt * 8 + 2 * kin;
            float b0v = __ldg(&bias[col]), b1v = __ldg(&bias[col + 1]);
            float v0 = acc[mt][nt][0] + b0v;
            float v1 = acc[mt][nt][1] + b1v;
            float v2 = acc[mt][nt][2] + b0v;
            float v3 = acc[mt][nt][3] + b1v;
            if (GELU) { v0 = gelu_exact(v0); v1 = gelu_exact(v1); v2 = gelu_exact(v2); v3 = gelu_exact(v3); }
            *(float2*)&C[(size_t)row * 512 + col] = make_float2(v0, v1);
            *(float2*)&C[(size_t)(row + 8) * 512 + col] = make_float2(v2, v3);
        }
    }
}

__global__ void __launch_bounds__(256) k_gemm1(const float* __restrict__ bias) {
    gemm_body<true>(g_feat1, g_w1, bias, g_h1);
}
__global__ void __launch_bounds__(256) k_gemm2(const float* __restrict__ bias, float* __restrict__ out) {
    gemm_body<false>(g_pool, g_w2, bias, out);
}

// ---------------- launch ----------------
extern "C" void kernel_launch(void* const* d_in, const int* in_sizes, int n_in,
                              void* d_out, int out_size) {
    const float*    x   = (const float*)d_in[0];
    const unsigned* eiw = (const unsigned*)d_in[1];
    const float*    wl1 = (const float*)d_in[2];
    const float*    wr1 = (const float*)d_in[3];
    const float*    b1  = (const float*)d_in[4];
    const float*    wl2 = (const float*)d_in[5];
    const float*    wr2 = (const float*)d_in[6];
    const float*    b2  = (const float*)d_in[7];
    float* out = (float*)d_out;

    const int TB = 256;
    const int node_warp_blocks = (NN * 32) / TB;

    k_zero_scan<<<(NN + TB - 1) / TB, TB>>>(eiw);
    k_convert<<<(EE + TB - 1) / TB, TB>>>(eiw);
    k_prep<<<(GD * 256 + TB - 1) / TB, TB>>>((const float4*)wl1, (const float4*)wr1,
                                             (const float4*)wl2, (const float4*)wr2);
    k_lap_gather<<<node_warp_blocks, TB>>>((const float4*)x);
    k_agg1_gather<<<node_warp_blocks, TB>>>();
    k_gemm1<<<dim3(4, NN / 128), TB>>>(b1);
    k_agg2_gather<<<node_warp_blocks, TB>>>();
    k_pool<<<dim3(BB, 4), 128>>>();
    k_gemm2<<<dim3(4, BB / 128), TB>>>(b2, out);
}

// round 16
// speedup vs baseline: 1.0030x; 1.0030x over previous
#include <cuda_runtime.h>
#include <cuda_fp16.h>
#include <math.h>
#include <stdint.h>

// Problem constants
#define NN 49152
#define EE 196608
#define BB 1024
#define SS 48
#define DD 256
#define GD 512
#define KDIM 1024
#define CAP 32

// ---------------- scratch ----------------
__device__ unsigned g_odd_or;
__device__ __align__(16) int g_degi[NN];
__device__ __align__(16) int g_cnti[NN];
__device__ __align__(16) int g_brow[NN * CAP];
__device__ __align__(16) int g_bdst[NN * CAP];
__device__ __align__(16) float g_dinv[NN];
__device__ __align__(16) float g_cntinv[NN];
__device__ __align__(16) float g_feat1[(size_t)NN * 1024];
__device__ __align__(16) float g_h1[(size_t)NN * 512];
__device__ __align__(16) float g_agg2[(size_t)NN * 512];
__device__ __align__(16) float g_pool[(size_t)BB * 1024];
__device__ __align__(16) float g_w1[(size_t)GD * KDIM];
__device__ __align__(16) float g_w2[(size_t)GD * KDIM];

// ---------------- helpers ----------------
__device__ __forceinline__ float gelu_exact(float x) {
    return 0.5f * x * (1.0f + erff(x * 0.7071067811865476f));
}
__device__ __forceinline__ void fma4(float4& a, float w, float4 v) {
    a.x = fmaf(w, v.x, a.x); a.y = fmaf(w, v.y, a.y);
    a.z = fmaf(w, v.z, a.z); a.w = fmaf(w, v.w, a.w);
}
__device__ __forceinline__ void add4(float4& a, float4 v) {
    a.x += v.x; a.y += v.y; a.z += v.z; a.w += v.w;
}
__device__ __forceinline__ float4 mul4(float4 a, float s) {
    return make_float4(a.x * s, a.y * s, a.z * s, a.w * s);
}
__device__ __forceinline__ unsigned h2pack(float a, float b) {
    __half2 h = __floats2half2_rn(a, b);
    return *(unsigned*)&h;
}

// ---------------- edge prep ----------------
__global__ void k_zero_scan(const unsigned* __restrict__ buf) {
    int t = blockIdx.x * blockDim.x + threadIdx.x;
    if (t == 0) g_odd_or = 0u;
    if (t < NN) { g_degi[t] = 0; g_cnti[t] = 0; }
    unsigned v = 0u;
    for (int i = t; i < EE; i += gridDim.x * blockDim.x)
        v |= buf[2 * i + 1];
    v = __reduce_or_sync(0xffffffffu, v);
    if ((threadIdx.x & 31) == 0 && v) atomicOr((unsigned*)&g_odd_or, v);
}

__global__ void k_convert(const unsigned* __restrict__ buf) {
    int e = blockIdx.x * blockDim.x + threadIdx.x;
    if (e >= EE) return;
    bool is64 = (g_odd_or == 0u);
    int r, c;
    if (is64) { r = (int)buf[2 * e]; c = (int)buf[2 * (EE + e)]; }
    else      { r = (int)buf[e];     c = (int)buf[EE + e]; }
    r = min(max(r, 0), NN - 1);
    c = min(max(c, 0), NN - 1);
    int p = atomicAdd(&g_degi[r], 1);
    if (p < CAP) g_brow[r * CAP + p] = c;
    int q = atomicAdd(&g_cnti[c], 1);
    if (q < CAP) g_bdst[c * CAP + q] = r;
}

__global__ void k_prep(const float4* __restrict__ wl1, const float4* __restrict__ wr1,
                       const float4* __restrict__ wl2, const float4* __restrict__ wr2) {
    int idx = blockIdx.x * blockDim.x + threadIdx.x;
    if (idx < NN) {
        int d = g_degi[idx];
        g_dinv[idx] = d > 0 ? rsqrtf((float)d) : 0.f;
        int c = g_cnti[idx];
        g_cntinv[idx] = 1.0f / (float)max(c, 1);
    }
    if (idx < GD * 256) {
        int j = idx >> 8, q = idx & 255;
        float4 v1 = (q < 128) ? __ldg(&wl1[(size_t)j * 128 + q]) : __ldg(&wr1[(size_t)j * 128 + q - 128]);
        float4 v2 = (q < 128) ? __ldg(&wl2[(size_t)j * 128 + q]) : __ldg(&wr2[(size_t)j * 128 + q - 128]);
        ((float4*)g_w1)[idx] = v1;
        ((float4*)g_w2)[idx] = v2;
    }
}

// ---------------- gathers ----------------
__global__ void k_lap_gather(const float4* __restrict__ x4) {
    int n = (blockIdx.x * blockDim.x + threadIdx.x) >> 5;
    int lane = threadIdx.x & 31;
    if (n >= NN) return;
    float dr = g_dinv[n];
    int deg = min(g_degi[n], CAP);
    float4 a0 = __ldg(&x4[(size_t)n * 64 + lane]);
    float4 a1 = __ldg(&x4[(size_t)n * 64 + 32 + lane]);
    float4 s0 = a0, s1 = a1;
    for (int j = 0; j < deg; j++) {
        int c = g_brow[n * CAP + j];
        float wt = -dr * g_dinv[c];
        fma4(s0, wt, __ldg(&x4[(size_t)c * 64 + lane]));
        fma4(s1, wt, __ldg(&x4[(size_t)c * 64 + 32 + lane]));
    }
    float4* dst = (float4*)(g_feat1 + (size_t)n * 1024);
    dst[128 + lane] = a0;
    dst[160 + lane] = a1;
    dst[192 + lane] = s0;
    dst[224 + lane] = s1;
}

__global__ void k_agg1_gather() {
    int n = (blockIdx.x * blockDim.x + threadIdx.x) >> 5;
    int lane = threadIdx.x & 31;
    if (n >= NN) return;
    int cnt = min(g_cnti[n], CAP);
    float4 acc0 = make_float4(0, 0, 0, 0), acc1 = acc0, acc2 = acc0, acc3 = acc0;
    for (int j = 0; j < cnt; j++) {
        int s = g_bdst[n * CAP + j];
        const float4* src = (const float4*)(g_feat1 + (size_t)s * 1024 + 512);
        add4(acc0, __ldg(src + lane));
        add4(acc1, __ldg(src + 32 + lane));
        add4(acc2, __ldg(src + 64 + lane));
        add4(acc3, __ldg(src + 96 + lane));
    }
    float ci = g_cntinv[n];
    float4* dst = (float4*)(g_feat1 + (size_t)n * 1024);
    dst[lane]      = mul4(acc0, ci);
    dst[32 + lane] = mul4(acc1, ci);
    dst[64 + lane] = mul4(acc2, ci);
    dst[96 + lane] = mul4(acc3, ci);
}

__global__ void k_agg2_gather() {
    int n = (blockIdx.x * blockDim.x + threadIdx.x) >> 5;
    int lane = threadIdx.x & 31;
    if (n >= NN) return;
    int cnt = min(g_cnti[n], CAP);
    float4 acc0 = make_float4(0, 0, 0, 0), acc1 = acc0, acc2 = acc0, acc3 = acc0;
    for (int j = 0; j < cnt; j++) {
        int s = g_bdst[n * CAP + j];
        const float4* src = (const float4*)(g_h1 + (size_t)s * 512);
        add4(acc0, __ldg(src + lane));
        add4(acc1, __ldg(src + 32 + lane));
        add4(acc2, __ldg(src + 64 + lane));
        add4(acc3, __ldg(src + 96 + lane));
    }
    float ci = g_cntinv[n];
    float4* dst = (float4*)(g_agg2 + (size_t)n * 512);
    dst[lane]      = mul4(acc0, ci);
    dst[32 + lane] = mul4(acc1, ci);
    dst[64 + lane] = mul4(acc2, ci);
    dst[96 + lane] = mul4(acc3, ci);
}

__global__ void k_pool() {
    int b = blockIdx.x;
    int f = blockIdx.y * 128 + threadIdx.x;
    float s1 = 0.f, s2 = 0.f;
    int n0 = b * SS;
    #pragma unroll 4
    for (int s = 0; s < SS; s++) {
        int n = n0 + s;
        s1 += g_agg2[(size_t)n * 512 + f];
        s2 += g_h1[(size_t)n * 512 + f];
    }
    const float inv = 1.0f / 48.0f;
    g_pool[(size_t)b * 1024 + f] = s1 * inv;
    g_pool[(size_t)b * 1024 + 512 + f] = s2 * inv;
}

// ---------------- fp16 NT GEMM (m16n8k16), double-buffered smem ----------------
// C[M,512] = act(A[M,1024] @ W[512,1024]^T + bias)
// smem holds half2 words; fragment addressing identical to the proven tf32
// stride-20 conflict-free layout (reads stay 32-bit). fp16 mantissa (10 bits)
// == tf32 mantissa, fp32 HW accum -> same error class, 2x MMA throughput.
template <bool GELU>
__device__ __forceinline__ void gemm_body(const float* __restrict__ A,
                                          const float* __restrict__ W,
                                          const float* __restrict__ bias,
                                          float* __restrict__ C) {
    __shared__ unsigned Ah[2][128 * 20];  // half2 words, row stride 20
    __shared__ unsigned Bh[2][128 * 20];
    const int K = KDIM;
    int ntile = blockIdx.x, mtile = blockIdx.y;
    int row0 = mtile * 128, col0 = ntile * 128;
    int tid = threadIdx.x, lane = tid & 31, warp = tid >> 5;
    int wm = warp & 3, wn = warp >> 2;        // 4 m-warps x 2 n-warps
    int m_off = wm * 32, n_off = wn * 64;     // warp computes 32x64
    int g = lane >> 2, kin = lane & 3;
    int lrow = tid >> 1;                      // 0..127 (one smem row per 2 threads)
    int lcb = tid & 1;                        // col block: halfpairs 0-7 / 8-15

    const float* aptr = A + (size_t)(row0 + lrow) * K + lcb * 16;
    const float* bptr = W + (size_t)(col0 + lrow) * K + lcb * 16;

    float acc[2][8][4];
    #pragma unroll
    for (int mt = 0; mt < 2; mt++)
        #pragma unroll
        for (int nt = 0; nt < 8; nt++)
            #pragma unroll
            for (int i = 0; i < 4; i++) acc[mt][nt][i] = 0.f;

    // store 16 floats (4 float4) as 8 half2 -> 2 STS.128
    auto stage = [&](unsigned* dstbase, const float4* ra) {
        uint4 lo, hi;
        lo.x = h2pack(ra[0].x, ra[0].y); lo.y = h2pack(ra[0].z, ra[0].w);
        lo.z = h2pack(ra[1].x, ra[1].y); lo.w = h2pack(ra[1].z, ra[1].w);
        hi.x = h2pack(ra[2].x, ra[2].y); hi.y = h2pack(ra[2].z, ra[2].w);
        hi.z = h2pack(ra[3].x, ra[3].y); hi.w = h2pack(ra[3].z, ra[3].w);
        uint4* s = (uint4*)(dstbase + lrow * 20 + lcb * 8);
        s[0] = lo; s[1] = hi;
    };

    // prologue: K-tile 0 -> buffer 0
    {
        float4 ra[4], rb[4];
        #pragma unroll
        for (int i = 0; i < 4; i++) {
            ra[i] = *(const float4*)(aptr + i * 4);
            rb[i] = *(const float4*)(bptr + i * 4);
        }
        stage(Ah[0], ra);
        stage(Bh[0], rb);
    }
    __syncthreads();

    int cur = 0;
    for (int kt = 0; kt < K; kt += 32) {
        bool has_next = (kt + 32 < K);
        float4 ra[4], rb[4];
        if (has_next) {
            #pragma unroll
            for (int i = 0; i < 4; i++) {
                ra[i] = *(const float4*)(aptr + kt + 32 + i * 4);
                rb[i] = *(const float4*)(bptr + kt + 32 + i * 4);
            }
        }

        #pragma unroll
        for (int kk = 0; kk < 2; kk++) {   // two K=16 steps per 32-float tile
            unsigned af[2][4];
            #pragma unroll
            for (int mt = 0; mt < 2; mt++) {
                int mr = m_off + mt * 16 + g;
                af[mt][0] = Ah[cur][mr * 20 + kk * 8 + kin];
                af[mt][1] = Ah[cur][(mr + 8) * 20 + kk * 8 + kin];
                af[mt][2] = Ah[cur][mr * 20 + kk * 8 + kin + 4];
                af[mt][3] = Ah[cur][(mr + 8) * 20 + kk * 8 + kin + 4];
            }
            #pragma unroll
            for (int nt = 0; nt < 8; nt++) {
                int nr = n_off + nt * 8 + g;
                unsigned bf0 = Bh[cur][nr * 20 + kk * 8 + kin];
                unsigned bf1 = Bh[cur][nr * 20 + kk * 8 + kin + 4];
                #pragma unroll
                for (int mt = 0; mt < 2; mt++) {
                    asm volatile(
                        "mma.sync.aligned.m16n8k16.row.col.f32.f16.f16.f32 "
                        "{%0,%1,%2,%3}, {%4,%5,%6,%7}, {%8,%9}, {%0,%1,%2,%3};"
                        : "+f"(acc[mt][nt][0]), "+f"(acc[mt][nt][1]),
                          "+f"(acc[mt][nt][2]), "+f"(acc[mt][nt][3])
                        : "r"(af[mt][0]), "r"(af[mt][1]), "r"(af[mt][2]), "r"(af[mt][3]),
                          "r"(bf0), "r"(bf1));
                }
            }
        }

        if (has_next) {
            int nxt = cur ^ 1;
            stage(Ah[nxt], ra);
            stage(Bh[nxt], rb);
            __syncthreads();
            cur = nxt;
        }
    }

    // epilogue: bias (+gelu), write [M,512] — accumulator layout same as m16n8k8
    #pragma unroll
    for (int mt = 0; mt < 2; mt++) {
        int row = row0 + m_off + mt * 16 + g;
        #pragma unroll
        for (int nt = 0; nt < 8; nt++) {
            int col = col0 + n_off + nt * 8 + 2 * kin;
            float b0v = __ldg(&bias[col]), b1v = __ldg(&bias[col + 1]);
            float v0 = acc[mt][nt][0] + b0v;
            float v1 = acc[mt][nt][1] + b1v;
            float v2 = acc[mt][nt][2] + b0v;
            float v3 = acc[mt][nt][3] + b1v;
            if (GELU) { v0 = gelu_exact(v0); v1 = gelu_exact(v1); v2 = gelu_exact(v2); v3 = gelu_exact(v3); }
            *(float2*)&C[(size_t)row * 512 + col] = make_float2(v0, v1);
            *(float2*)&C[(size_t)(row + 8) * 512 + col] = make_float2(v2, v3);
        }
    }
}

__global__ void __launch_bounds__(256) k_gemm1(const float* __restrict__ bias) {
    gemm_body<true>(g_feat1, g_w1, bias, g_h1);
}
__global__ void __launch_bounds__(256) k_gemm2(const float* __restrict__ bias, float* __restrict__ out) {
    gemm_body<false>(g_pool, g_w2, bias, out);
}

// ---------------- launch ----------------
extern "C" void kernel_launch(void* const* d_in, const int* in_sizes, int n_in,
                              void* d_out, int out_size) {
    const float*    x   = (const float*)d_in[0];
    const unsigned* eiw = (const unsigned*)d_in[1];
    const float*    wl1 = (const float*)d_in[2];
    const float*    wr1 = (const float*)d_in[3];
    const float*    b1  = (const float*)d_in[4];
    const float*    wl2 = (const float*)d_in[5];
    const float*    wr2 = (const float*)d_in[6];
    const float*    b2  = (const float*)d_in[7];
    float* out = (float*)d_out;

    const int TB = 256;
    const int node_warp_blocks = (NN * 32) / TB;

    k_zero_scan<<<(NN + TB - 1) / TB, TB>>>(eiw);
    k_convert<<<(EE + TB - 1) / TB, TB>>>(eiw);
    k_prep<<<(GD * 256 + TB - 1) / TB, TB>>>((const float4*)wl1, (const float4*)wr1,
                                             (const float4*)wl2, (const float4*)wr2);
    k_lap_gather<<<node_warp_blocks, TB>>>((const float4*)x);
    k_agg1_gather<<<node_warp_blocks, TB>>>();
    k_gemm1<<<dim3(4, NN / 128), TB>>>(b1);
    k_agg2_gather<<<node_warp_blocks, TB>>>();
    k_pool<<<dim3(BB, 4), 128>>>();
    k_gemm2<<<dim3(4, BB / 128), TB>>>(b2, out);
}